// round 15
// baseline (speedup 1.0000x reference)
#include <cuda_runtime.h>
#include <cuda_bf16.h>
#include <math.h>

#define N_GAUSS 2048
#define HEIGHT  192
#define WIDTH   192
#define HW      (HEIGHT*WIDTH)
#define ALPHA_MIN (1.0f/255.0f)
#define NSEG    16
#define SEG     (N_GAUSS / NSEG)   // 128
#define NGRP    (SEG / 32)         // 4 cull groups per segment
#define TILE_W  16
#define TILE_H  8
#define TPX     128                 // pixels per tile

// Depth-sorted gaussian data, exp2-domain (80 KB total -> L1/L2 resident)
__device__ float4 g_A[N_GAUSS];  // mx, my, 0.5*a*log2e, b*log2e
__device__ float4 g_B[N_GAUSS];  // 0.5*c*log2e, log2(op), col_r, col_g
__device__ float2 g_C[N_GAUSS];  // col_b, pad
__device__ float4 g_D[N_GAUSS];  // mx, my, rx, ry : packed cull record

// ---------------------------------------------------------------------------
// Kernel 1: rank-by-counting sort, one warp per gaussian, single wave
// (128 blocks x 512 threads). Order lexicographic (depth, index).
// ---------------------------------------------------------------------------
__global__ void __launch_bounds__(512)
sort_scatter_kernel(const float* __restrict__ means2d,
                    const float* __restrict__ conics,
                    const float* __restrict__ colors,
                    const float* __restrict__ opacities,
                    const float* __restrict__ depths)
{
    __shared__ float sd[N_GAUSS];
    const int tid  = threadIdx.x;
    const int warp = tid >> 5, lane = tid & 31;
    const int gid  = blockIdx.x * 16 + warp;

    // Hoisted param loads (lane 0; overlaps staging + count latency).
    float p_mx, p_my, p_ca, p_cb, p_cc, p_op, p_cr, p_cg, p_cbl;
    if (lane == 0) {
        p_mx = means2d[2*gid + 0];
        p_my = means2d[2*gid + 1];
        p_ca = conics[3*gid + 0];
        p_cb = conics[3*gid + 1];
        p_cc = conics[3*gid + 2];
        p_op = opacities[gid];
        p_cr = colors[3*gid + 0];
        p_cg = colors[3*gid + 1];
        p_cbl= colors[3*gid + 2];
    }

    #pragma unroll
    for (int i = tid; i < N_GAUSS; i += 512)
        sd[i] = depths[i];
    __syncthreads();

    const float myd = sd[gid];
    int c = 0;
    #pragma unroll 16
    for (int k = 0; k < N_GAUSS / 32; ++k) {
        int i = k * 32 + lane;
        float d = sd[i];
        c += (d < myd) || ((d == myd) && (i < gid));
    }
    int rank = __reduce_add_sync(0xffffffffu, c);

    if (lane == 0) {
        const float L2E = 1.4426950408889634f;
        // alpha >= 1/255 <=> sigma <= log(255*op); margin keeps the AABB
        // cull conservative vs the exact in-walk gate.
        float t = logf(255.0f * p_op) + 1e-4f;
        float det = p_ca * p_cc - p_cb * p_cb;
        float inv = 2.0f * fmaxf(t, 0.0f) / det;
        float rx = sqrtf(fmaxf(inv * p_cc, 0.0f)) + 1e-3f;
        float ry = sqrtf(fmaxf(inv * p_ca, 0.0f)) + 1e-3f;
        // exp2-domain: alpha = 2^(log2(op) - s2), s2 = sigma*log2e
        g_A[rank] = make_float4(p_mx, p_my, 0.5f * p_ca * L2E, p_cb * L2E);
        g_B[rank] = make_float4(0.5f * p_cc * L2E, log2f(p_op), p_cr, p_cg);
        g_C[rank] = make_float2(p_cbl, 0.0f);
        g_D[rank] = make_float4(p_mx, p_my, rx, ry);
    }
}

// ---------------------------------------------------------------------------
// Kernel 2 (fused render + combine): 16x8 px tile per block, 512 threads =
// 16 warps = 16 depth segments, 4 px/thread (fully scalarized chains).
// Phase-split cull (4 overlapped LDG.128 ballots), exact in-order 2-wide
// survivor walk in exp2 domain (no op-multiply, no log2e-multiply, no
// ALPHA_MAX clamp -- provably dead under the s>0 gate since op<=0.95).
// ---------------------------------------------------------------------------
__global__ void __launch_bounds__(512, 2)
render_fused_kernel(const float* __restrict__ background, float* __restrict__ out)
{
    __shared__ float4 smP[NSEG][TPX];  // (accR, accG, accB, T_seg) per pixel

    const int tid  = threadIdx.x;
    const int seg  = tid >> 5;           // 0..15 : warp == segment
    const int lane = tid & 31;
    const int base = seg * SEG;

    const int tx0 = blockIdx.x * TILE_W;
    const int ty0 = blockIdx.y * TILE_H;
    const int xl  = lane & 15;           // 0..15
    const int yb  = (lane >> 4) * 4;     // 0 or 4
    const float px  = (float)(tx0 + xl) + 0.5f;
    const float py0 = (float)(ty0 + yb) + 0.5f;
    const float py1 = py0 + 1.0f, py2 = py0 + 2.0f, py3 = py0 + 3.0f;

    // Whole-tile pixel-center bounds (cull granularity = tile).
    const float sxmin = tx0 + 0.5f;
    const float sxmax = tx0 + TILE_W - 0.5f;
    const float symin = ty0 + 0.5f;
    const float symax = ty0 + TILE_H - 0.5f;

    // Phase 1: independent cull burst — all group ballots up front.
    unsigned masks[NGRP];
    #pragma unroll
    for (int k = 0; k < NGRP; ++k) {
        float4 d = g_D[base + k * 32 + lane];
        bool pred = (d.x - d.z <= sxmax) & (d.x + d.z >= sxmin) &
                    (d.y - d.w <= symax) & (d.y + d.w >= symin);
        masks[k] = __ballot_sync(0xffffffffu, pred);
    }

    // Phase 2: exact, in-order, 2-wide survivor walk; 4 scalar pixel chains.
    float T0 = 1.0f, T1 = 1.0f, T2 = 1.0f, T3 = 1.0f;
    float r0 = 0, g0 = 0, b0 = 0;
    float r1 = 0, g1 = 0, b1 = 0;
    float r2 = 0, g2 = 0, b2 = 0;
    float r3 = 0, g3 = 0, b3 = 0;

    #pragma unroll
    for (int k = 0; k < NGRP; ++k) {
        unsigned mask = masks[k];
        const int gbase = base + k * 32;
        while (mask) {
            int j0 = gbase + (__ffs(mask) - 1);
            mask &= mask - 1;
            bool two = (mask != 0);
            int j1 = two ? (gbase + (__ffs(mask) - 1)) : j0;
            if (two) mask &= mask - 1;

            float4 A0 = g_A[j0], A1 = g_A[j1];
            float4 B0 = g_B[j0], B1 = g_B[j1];
            float2 C0 = g_C[j0], C1 = g_C[j1];

            // dx terms shared across the 4 rows (exp2 domain).
            float dx0 = px - A0.x;
            float qa0 = A0.z * dx0 * dx0;
            float bx0 = A0.w * dx0;
            float dx1 = px - A1.x;
            float qa1 = A1.z * dx1 * dx1;
            float bx1 = A1.w * dx1;

#define ROWSTEP(PY, TR, RR, GG, BB)                                          \
            {                                                                \
                float dy0 = (PY) - A0.y, dy1 = (PY) - A1.y;                  \
                float s0 = qa0 + (B0.x * dy0 + bx0) * dy0;                   \
                float s1 = qa1 + (B1.x * dy1 + bx1) * dy1;                   \
                float a0 = exp2f(B0.y - s0);                                 \
                float a1 = exp2f(B1.y - s1);                                 \
                a0 = ((s0 > 0.0f) & (a0 >= ALPHA_MIN)) ? a0 : 0.0f;          \
                a1 = ((s1 > 0.0f) & (a1 >= ALPHA_MIN) & two) ? a1 : 0.0f;    \
                float w = (TR) * a0;                                         \
                RR = fmaf(w, B0.z, RR);                                      \
                GG = fmaf(w, B0.w, GG);                                      \
                BB = fmaf(w, C0.x, BB);                                      \
                TR *= (1.0f - a0);                                           \
                w = (TR) * a1;                                               \
                RR = fmaf(w, B1.z, RR);                                      \
                GG = fmaf(w, B1.w, GG);                                      \
                BB = fmaf(w, C1.x, BB);                                      \
                TR *= (1.0f - a1);                                           \
            }
            ROWSTEP(py0, T0, r0, g0, b0)
            ROWSTEP(py1, T1, r1, g1, b1)
            ROWSTEP(py2, T2, r2, g2, b2)
            ROWSTEP(py3, T3, r3, g3, b3)
#undef ROWSTEP
        }
    }

    smP[seg][(yb + 0) * TILE_W + xl] = make_float4(r0, g0, b0, T0);
    smP[seg][(yb + 1) * TILE_W + xl] = make_float4(r1, g1, b1, T1);
    smP[seg][(yb + 2) * TILE_W + xl] = make_float4(r2, g2, b2, T2);
    smP[seg][(yb + 3) * TILE_W + xl] = make_float4(r3, g3, b3, T3);
    __syncthreads();

    // Fold the 16 segments front-to-back + background (threads 0..127).
    if (tid < TPX) {
        float fr = 0.0f, fg = 0.0f, fb = 0.0f, fT = 1.0f;
        #pragma unroll
        for (int s = 0; s < NSEG; ++s) {
            float4 v = smP[s][tid];
            fr = fmaf(fT, v.x, fr);
            fg = fmaf(fT, v.y, fg);
            fb = fmaf(fT, v.z, fb);
            fT *= v.w;
        }
        const int pix = (ty0 + (tid >> 4)) * WIDTH + tx0 + (tid & 15);
        out[0 * HW + pix] = fmaf(background[0], fT, fr);
        out[1 * HW + pix] = fmaf(background[1], fT, fg);
        out[2 * HW + pix] = fmaf(background[2], fT, fb);
    }
}

// ---------------------------------------------------------------------------
extern "C" void kernel_launch(void* const* d_in, const int* in_sizes, int n_in,
                              void* d_out, int out_size)
{
    const float* means2d    = (const float*)d_in[0];
    const float* conics     = (const float*)d_in[1];
    const float* colors     = (const float*)d_in[2];
    const float* opacities  = (const float*)d_in[3];
    const float* depths     = (const float*)d_in[4];
    const float* background = (const float*)d_in[5];
    float* out = (float*)d_out;

    sort_scatter_kernel<<<N_GAUSS / 16, 512>>>(means2d, conics, colors, opacities, depths);
    dim3 grid(WIDTH / TILE_W, HEIGHT / TILE_H);
    render_fused_kernel<<<grid, 512>>>(background, out);
}

// round 16
// speedup vs baseline: 1.1597x; 1.1597x over previous
#include <cuda_runtime.h>
#include <cuda_bf16.h>
#include <math.h>

#define N_GAUSS 2048
#define HEIGHT  192
#define WIDTH   192
#define HW      (HEIGHT*WIDTH)
#define ALPHA_MIN (1.0f/255.0f)
#define NSEG    16
#define SEG     (N_GAUSS / NSEG)   // 128
#define NGRP    (SEG / 32)         // 4 cull groups per segment
#define TILE_W  16
#define TILE_H  8
#define TPX     128                 // pixels per tile

// Depth-sorted gaussian data, exp2-domain (80 KB total -> L1/L2 resident)
__device__ float4 g_A[N_GAUSS];  // mx, my, 0.5*a*log2e, b*log2e
__device__ float4 g_B[N_GAUSS];  // 0.5*c*log2e, log2(op), col_r, col_g
__device__ float2 g_C[N_GAUSS];  // col_b, pad
__device__ float4 g_D[N_GAUSS];  // mx, my, rx, ry : packed cull record

// ---------------------------------------------------------------------------
// Kernel 1: rank-by-counting sort, one warp per gaussian, single wave
// (128 blocks x 512 threads). Order lexicographic (depth, index).
// ---------------------------------------------------------------------------
__global__ void __launch_bounds__(512)
sort_scatter_kernel(const float* __restrict__ means2d,
                    const float* __restrict__ conics,
                    const float* __restrict__ colors,
                    const float* __restrict__ opacities,
                    const float* __restrict__ depths)
{
    __shared__ float sd[N_GAUSS];
    const int tid  = threadIdx.x;
    const int warp = tid >> 5, lane = tid & 31;
    const int gid  = blockIdx.x * 16 + warp;

    // Hoisted param loads (lane 0; overlaps staging + count latency).
    float p_mx, p_my, p_ca, p_cb, p_cc, p_op, p_cr, p_cg, p_cbl;
    if (lane == 0) {
        p_mx = means2d[2*gid + 0];
        p_my = means2d[2*gid + 1];
        p_ca = conics[3*gid + 0];
        p_cb = conics[3*gid + 1];
        p_cc = conics[3*gid + 2];
        p_op = opacities[gid];
        p_cr = colors[3*gid + 0];
        p_cg = colors[3*gid + 1];
        p_cbl= colors[3*gid + 2];
    }

    #pragma unroll
    for (int i = tid; i < N_GAUSS; i += 512)
        sd[i] = depths[i];
    __syncthreads();

    const float myd = sd[gid];
    int c = 0;
    #pragma unroll 16
    for (int k = 0; k < N_GAUSS / 32; ++k) {
        int i = k * 32 + lane;
        float d = sd[i];
        c += (d < myd) || ((d == myd) && (i < gid));
    }
    int rank = __reduce_add_sync(0xffffffffu, c);

    if (lane == 0) {
        const float L2E = 1.4426950408889634f;
        // alpha >= 1/255 <=> sigma <= log(255*op); margin keeps the AABB
        // cull conservative vs the exact in-walk gate.
        float t = logf(255.0f * p_op) + 1e-4f;
        float det = p_ca * p_cc - p_cb * p_cb;
        float inv = 2.0f * fmaxf(t, 0.0f) / det;
        float rx = sqrtf(fmaxf(inv * p_cc, 0.0f)) + 1e-3f;
        float ry = sqrtf(fmaxf(inv * p_ca, 0.0f)) + 1e-3f;
        // exp2-domain: alpha = 2^(log2(op) - sigma*log2e)
        g_A[rank] = make_float4(p_mx, p_my, 0.5f * p_ca * L2E, p_cb * L2E);
        g_B[rank] = make_float4(0.5f * p_cc * L2E, log2f(p_op), p_cr, p_cg);
        g_C[rank] = make_float2(p_cbl, 0.0f);
        g_D[rank] = make_float4(p_mx, p_my, rx, ry);
    }
}

// ---------------------------------------------------------------------------
// Kernel 2 (fused render + combine): 16x8 px tile per block, 512 threads =
// 16 warps = 16 depth segments, 4 px/thread. Register-lean 1-wide survivor
// walk (ILP comes from the 4 independent pixel chains), phase-split cull,
// smem fold after one barrier. min 3 blocks/SM for issue-rate headroom.
// ---------------------------------------------------------------------------
__global__ void __launch_bounds__(512, 3)
render_fused_kernel(const float* __restrict__ background, float* __restrict__ out)
{
    __shared__ float4 smP[NSEG][TPX];  // (accR, accG, accB, T_seg) per pixel

    const int tid  = threadIdx.x;
    const int seg  = tid >> 5;           // 0..15 : warp == segment
    const int lane = tid & 31;
    const int base = seg * SEG;

    const int tx0 = blockIdx.x * TILE_W;
    const int ty0 = blockIdx.y * TILE_H;
    const int xl  = lane & 15;           // 0..15
    const int yb  = (lane >> 4) * 4;     // 0 or 4
    const float px  = (float)(tx0 + xl) + 0.5f;
    const float pyb = (float)(ty0 + yb) + 0.5f;

    // Phase 1: independent cull burst — all group ballots up front.
    unsigned masks[NGRP];
    {
        const float sxmin = tx0 + 0.5f;
        const float sxmax = tx0 + TILE_W - 0.5f;
        const float symin = ty0 + 0.5f;
        const float symax = ty0 + TILE_H - 0.5f;
        #pragma unroll
        for (int k = 0; k < NGRP; ++k) {
            float4 d = g_D[base + k * 32 + lane];
            bool pred = (d.x - d.z <= sxmax) & (d.x + d.z >= sxmin) &
                        (d.y - d.w <= symax) & (d.y + d.w >= symin);
            masks[k] = __ballot_sync(0xffffffffu, pred);
        }
    }

    // Phase 2: exact, in-order, 1-wide survivor walk; 4 scalar pixel chains.
    float T0 = 1.0f, T1 = 1.0f, T2 = 1.0f, T3 = 1.0f;
    float r0 = 0, g0 = 0, b0 = 0;
    float r1 = 0, g1 = 0, b1 = 0;
    float r2 = 0, g2 = 0, b2 = 0;
    float r3 = 0, g3 = 0, b3 = 0;

    #pragma unroll
    for (int k = 0; k < NGRP; ++k) {
        unsigned mask = masks[k];
        const int gbase = base + k * 32;
        while (mask) {
            int j = gbase + (__ffs(mask) - 1);
            mask &= mask - 1;

            float4 A = g_A[j];
            float4 B = g_B[j];
            float2 C = g_C[j];

            float dx  = px - A.x;
            float qa  = A.z * dx * dx;      // 0.5a' dx^2
            float bx  = A.w * dx;           // b' dx
            float oq  = B.y - qa;           // lop2 - 0.5a' dx^2
            float dy  = pyb - A.y;

#define ROWSTEP(TR, RR, GG, BB)                                              \
            {                                                                \
                float t2  = fmaf(B.x, dy, bx);        /* c'dy + b'dx  */     \
                float arg = fmaf(-t2, dy, oq);        /* lop2 - sigma2 */    \
                float a   = exp2f(arg);                                      \
                /* sigma2>0 <=> arg<lop2 ; alpha>=1/255 : exact ref gate */  \
                a = ((arg < B.y) & (a >= ALPHA_MIN)) ? a : 0.0f;             \
                float w = (TR) * a;                                          \
                RR = fmaf(w, B.z, RR);                                       \
                GG = fmaf(w, B.w, GG);                                       \
                BB = fmaf(w, C.x, BB);                                       \
                TR = fmaf(-(TR), a, TR);                                     \
            }
            ROWSTEP(T0, r0, g0, b0) dy += 1.0f;
            ROWSTEP(T1, r1, g1, b1) dy += 1.0f;
            ROWSTEP(T2, r2, g2, b2) dy += 1.0f;
            ROWSTEP(T3, r3, g3, b3)
#undef ROWSTEP
        }
    }

    smP[seg][(yb + 0) * TILE_W + xl] = make_float4(r0, g0, b0, T0);
    smP[seg][(yb + 1) * TILE_W + xl] = make_float4(r1, g1, b1, T1);
    smP[seg][(yb + 2) * TILE_W + xl] = make_float4(r2, g2, b2, T2);
    smP[seg][(yb + 3) * TILE_W + xl] = make_float4(r3, g3, b3, T3);
    __syncthreads();

    // Fold the 16 segments front-to-back + background (threads 0..127).
    if (tid < TPX) {
        float fr = 0.0f, fg = 0.0f, fb = 0.0f, fT = 1.0f;
        #pragma unroll
        for (int s = 0; s < NSEG; ++s) {
            float4 v = smP[s][tid];
            fr = fmaf(fT, v.x, fr);
            fg = fmaf(fT, v.y, fg);
            fb = fmaf(fT, v.z, fb);
            fT *= v.w;
        }
        const int pix = (ty0 + (tid >> 4)) * WIDTH + tx0 + (tid & 15);
        out[0 * HW + pix] = fmaf(background[0], fT, fr);
        out[1 * HW + pix] = fmaf(background[1], fT, fg);
        out[2 * HW + pix] = fmaf(background[2], fT, fb);
    }
}

// ---------------------------------------------------------------------------
extern "C" void kernel_launch(void* const* d_in, const int* in_sizes, int n_in,
                              void* d_out, int out_size)
{
    const float* means2d    = (const float*)d_in[0];
    const float* conics     = (const float*)d_in[1];
    const float* colors     = (const float*)d_in[2];
    const float* opacities  = (const float*)d_in[3];
    const float* depths     = (const float*)d_in[4];
    const float* background = (const float*)d_in[5];
    float* out = (float*)d_out;

    sort_scatter_kernel<<<N_GAUSS / 16, 512>>>(means2d, conics, colors, opacities, depths);
    dim3 grid(WIDTH / TILE_W, HEIGHT / TILE_H);
    render_fused_kernel<<<grid, 512>>>(background, out);
}